// round 3
// baseline (speedup 1.0000x reference)
#include <cuda_runtime.h>

#define NSAMPLE 32
#define MAXN 4096

// scratch (no allocation allowed)
__device__ int g_cnt[MAXN];
__device__ int g_off[MAXN];
__device__ int g_total;
__device__ int g_ball[MAXN * NSAMPLE];

// ---------------------------------------------------------------------------
// Pass 1: warp-per-point ball query with RoI pruning, ordered first-32 select
// (bit-identical arithmetic to the passing R1 version)
// ---------------------------------------------------------------------------
__global__ void query_kernel(const float* __restrict__ xyz,
                             const float* __restrict__ new_xyz,
                             const float* __restrict__ rois,
                             int N, int Nb, int M, int K) {
    int warp = (blockIdx.x * blockDim.x + threadIdx.x) >> 5;
    int lane = threadIdx.x & 31;
    if (warp >= N) return;
    int i = warp;

    float px = xyz[3 * i + 0];
    float py = xyz[3 * i + 1];
    float pz = xyz[3 * i + 2];
    int b = i / Nb;
    int MK = M * K;
    const float* roib  = rois    + (size_t)b * M * 7;
    const float* gridb = new_xyz + (size_t)b * MK * 3;

    int cnt = 0;
    int ngroups = (M + 31) >> 5;
    for (int g = 0; g < ngroups && cnt < NSAMPLE; ++g) {
        int r = (g << 5) + lane;
        bool ib = false;
        if (r < M) {
            const float* ro = roib + (size_t)r * 7;
            float dx = px - ro[0], dy = py - ro[1], dz = pz - ro[2];
            float d2b = __fadd_rn(__fadd_rn(__fmul_rn(dx, dx), __fmul_rn(dy, dy)), __fmul_rn(dz, dz));
            float r2  = __fadd_rn(__fadd_rn(__fmul_rn(ro[3], ro[3]), __fmul_rn(ro[4], ro[4])), __fmul_rn(ro[5], ro[5]));
            ib = (d2b <= r2);
        }
        unsigned rm = __ballot_sync(0xffffffffu, ib);
        while (rm && cnt < NSAMPLE) {
            int rb = __ffs(rm) - 1;
            rm &= rm - 1;
            int roi = (g << 5) + rb;
            int basej = roi * K;
            int nchunks = (K + 31) >> 5;
            for (int c = 0; c < nchunks && cnt < NSAMPLE; ++c) {
                int jl = (c << 5) + lane;
                int j = basej + jl;
                bool ok = false;
                if (jl < K) {
                    const float* gp = gridb + (size_t)j * 3;
                    float dx = px - gp[0], dy = py - gp[1], dz = pz - gp[2];
                    float d2 = __fadd_rn(__fadd_rn(__fmul_rn(dx, dx), __fmul_rn(dy, dy)), __fmul_rn(dz, dz));
                    ok = (d2 <= 1.0f);  // RADIUS^2
                }
                unsigned m = __ballot_sync(0xffffffffu, ok);
                int rank = cnt + __popc(m & ((1u << lane) - 1u));
                if (ok && rank < NSAMPLE)
                    g_ball[i * NSAMPLE + rank] = b * MK + j;
                cnt += __popc(m);
            }
        }
    }
    if (lane == 0) g_cnt[i] = cnt < NSAMPLE ? cnt : NSAMPLE;
}

// ---------------------------------------------------------------------------
// Pass 2: exclusive scan, 128 threads x 32 counts, warp scan + smem combine
// ---------------------------------------------------------------------------
__global__ void scan_kernel(int N) {
    __shared__ int warp_sums[4];
    int t = threadIdx.x;              // 0..127
    int lane = t & 31;
    int wid = t >> 5;
    const int PER = MAXN / 128;       // 32

    int base = t * PER;
    int vals[PER];
    int tot = 0;
#pragma unroll
    for (int k = 0; k < PER; ++k) {
        int idx = base + k;
        int v = (idx < N) ? g_cnt[idx] : 0;
        vals[k] = v;
        tot += v;
    }
    // inclusive warp scan of tot
    int inc = tot;
#pragma unroll
    for (int d = 1; d < 32; d <<= 1) {
        int y = __shfl_up_sync(0xffffffffu, inc, d);
        if (lane >= d) inc += y;
    }
    if (lane == 31) warp_sums[wid] = inc;
    __syncthreads();
    int wprefix = 0;
#pragma unroll
    for (int w = 0; w < 4; ++w)
        if (w < wid) wprefix += warp_sums[w];
    int run = wprefix + inc - tot;    // exclusive prefix for this thread's chunk
#pragma unroll
    for (int k = 0; k < PER; ++k) {
        int idx = base + k;
        if (idx < N) g_off[idx] = run;
        run += vals[k];
    }
    if (t == 127) g_total = wprefix + inc;
}

// ---------------------------------------------------------------------------
// Pass 3: block-per-point coalesced scatter + tail-zero blocks
// blocks [0, N)        : write point rows
// blocks [N, N+ZBLK)   : zero output tail [g_total, L)
// ---------------------------------------------------------------------------
#define SCT_THREADS 128
#define ZBLK 1024

__global__ void scatter_kernel(const float* __restrict__ xyz,
                               const float* __restrict__ new_xyz_flat,
                               const float* __restrict__ feat,
                               float* __restrict__ out_gf,
                               float* __restrict__ out_idx,
                               int N, int C, int L) {
    int blk = blockIdx.x;
    int t = threadIdx.x;
    int D = 3 + C;

    if (blk < N) {
        __shared__ int   sball[NSAMPLE];
        __shared__ float sval[67];   // [0..2]=xyz, [3..3+C)=features (C<=64)
        int i = blk;
        int cnt = g_cnt[i];
        if (cnt == 0) return;
        int off = g_off[i];

        if (t < cnt) sball[t] = g_ball[i * NSAMPLE + t];
        if (t < 3)   sval[t] = xyz[3 * i + t];
        if (t < C)   sval[3 + t] = feat[(size_t)i * C + t];
        __syncthreads();

        int total = cnt * D;
        float* dst = out_gf + (size_t)off * D;
        for (int e = t; e < total; e += SCT_THREADS) {
            int row = e / D;          // D=35 typ.
            int col = e - row * D;
            float v = sval[col];
            if (col < 3)
                v -= new_xyz_flat[(size_t)sball[row] * 3 + col];
            dst[e] = v;
        }
        if (t < cnt) out_idx[off + t] = (float)sball[t];
    } else {
        // tail zero
        int zb = blk - N;
        int nind = g_total;
        long S = (long)nind * D;
        long E = (long)L * D;
        long gt = (long)zb * SCT_THREADS + t;
        long TOT = (long)ZBLK * SCT_THREADS;
        // scalar head until 16B alignment of (out_gf + S)
        long S4 = (S + 3) & ~3L;
        if (S4 > E) S4 = E;
        if (gt < (S4 - S)) out_gf[S + gt] = 0.f;
        // vectorized body
        float4 z4 = make_float4(0.f, 0.f, 0.f, 0.f);
        long n4 = (E - S4) >> 2;
        float4* p4 = (float4*)(out_gf + S4);
        for (long q = gt; q < n4; q += TOT) p4[q] = z4;
        // remainder of gf region
        long rem = (E - S4) & 3L;
        if (gt < rem) out_gf[S4 + (n4 << 2) + gt] = 0.f;
        // idx tail
        long SI = nind, EI = L;
        for (long q = SI + gt; q < EI; q += TOT) out_idx[q] = 0.f;
    }
}

// ---------------------------------------------------------------------------
extern "C" void kernel_launch(void* const* d_in, const int* in_sizes, int n_in,
                              void* d_out, int out_size) {
    const float* xyz     = (const float*)d_in[0];
    // d_in[1] = xyz_batch_cnt (int32), only its length B is needed
    const float* new_xyz = (const float*)d_in[2];
    const float* rois    = (const float*)d_in[3];
    const float* feats   = (const float*)d_in[4];

    int N  = in_sizes[0] / 3;
    int B  = in_sizes[1];
    int Nb = N / B;
    int M  = in_sizes[3] / (B * 7);
    int K  = in_sizes[2] / (B * M * 3);
    int C  = in_sizes[4] / N;
    int L  = N * NSAMPLE;
    int D  = 3 + C;

    // Pass 1: ball query (warp per point)
    int nthreads = N * 32;
    query_kernel<<<(nthreads + 255) / 256, 256>>>(xyz, new_xyz, rois, N, Nb, M, K);

    // Pass 2: scan (single 128-thread block)
    scan_kernel<<<1, 128>>>(N);

    // Pass 3: scatter + tail zero
    scatter_kernel<<<N + ZBLK, SCT_THREADS>>>(
        xyz, new_xyz, feats,
        (float*)d_out, (float*)d_out + (size_t)L * D, N, C, L);
}

// round 4
// speedup vs baseline: 1.2354x; 1.2354x over previous
#include <cuda_runtime.h>

#define NSAMPLE 32
#define MAXN 4096
#define FULL 0xffffffffu

// scratch (no allocation allowed)
__device__ int g_cnt[MAXN];
__device__ int g_off[MAXN];
__device__ int g_total;
__device__ int g_ball[MAXN * NSAMPLE];
__device__ int g_arrive;   // zero-init; reset by last block each launch

// ---------------------------------------------------------------------------
// Fused query + scan. Warp-per-point; RoIs cached in smem; chunk loads batched
// for MLP; last arriving block performs the exclusive scan of g_cnt.
// Arithmetic for the comparisons is bit-identical to the passing R1 kernel.
// ---------------------------------------------------------------------------
template<int NCH>
__global__ void query_scan_kernel(const float* __restrict__ xyz,
                                  const float* __restrict__ new_xyz,
                                  const float* __restrict__ rois,
                                  int N, int Nb, int M, int K, int BM,
                                  int nblocks) {
    __shared__ float s_cx[1024], s_cy[1024], s_cz[1024], s_r2[1024];
    int tid = threadIdx.x;
    int lane = tid & 31;

    // preload all batches' RoIs (SoA, precomputed r^2 with exact op order)
    for (int e = tid; e < BM; e += blockDim.x) {
        const float* ro = rois + (size_t)e * 7;
        s_cx[e] = ro[0]; s_cy[e] = ro[1]; s_cz[e] = ro[2];
        s_r2[e] = __fadd_rn(__fadd_rn(__fmul_rn(ro[3], ro[3]),
                                      __fmul_rn(ro[4], ro[4])),
                            __fmul_rn(ro[5], ro[5]));
    }
    __syncthreads();

    int i = blockIdx.x * (blockDim.x >> 5) + (tid >> 5);
    if (i < N) {
        float px = xyz[3 * i + 0];
        float py = xyz[3 * i + 1];
        float pz = xyz[3 * i + 2];
        int b = i / Nb;
        int MK = M * K;
        const float* gridb = new_xyz + (size_t)b * MK * 3;
        int rbase = b * M;

        int cnt = 0;
        int ngroups = (M + 31) >> 5;
        for (int g = 0; g < ngroups && cnt < NSAMPLE; ++g) {
            int r = (g << 5) + lane;
            bool ib = false;
            if (r < M) {
                int e = rbase + r;
                float dx = px - s_cx[e], dy = py - s_cy[e], dz = pz - s_cz[e];
                float d2b = __fadd_rn(__fadd_rn(__fmul_rn(dx, dx), __fmul_rn(dy, dy)), __fmul_rn(dz, dz));
                ib = (d2b <= s_r2[e]);
            }
            unsigned rm = __ballot_sync(FULL, ib);
            while (rm && cnt < NSAMPLE) {
                int rb = __ffs(rm) - 1;
                rm &= rm - 1;
                int roi = (g << 5) + rb;
                int basej = roi * K;

                // batch all chunk loads first (high MLP), exact op order kept
                float d2s[NCH];
#pragma unroll
                for (int c = 0; c < NCH; ++c) {
                    int jl = (c << 5) + lane;
                    d2s[c] = 4.0f;  // > RADIUS^2 -> fails test
                    if (jl < K) {
                        const float* gp = gridb + (size_t)(basej + jl) * 3;
                        float dx = px - gp[0], dy = py - gp[1], dz = pz - gp[2];
                        d2s[c] = __fadd_rn(__fadd_rn(__fmul_rn(dx, dx), __fmul_rn(dy, dy)), __fmul_rn(dz, dz));
                    }
                }
                unsigned masks[NCH];
#pragma unroll
                for (int c = 0; c < NCH; ++c)
                    masks[c] = __ballot_sync(FULL, d2s[c] <= 1.0f);
#pragma unroll
                for (int c = 0; c < NCH; ++c) {
                    if (cnt < NSAMPLE) {
                        unsigned m = masks[c];
                        int rank = cnt + __popc(m & ((1u << lane) - 1u));
                        if (((m >> lane) & 1u) && rank < NSAMPLE)
                            g_ball[i * NSAMPLE + rank] = b * MK + basej + (c << 5) + lane;
                        cnt += __popc(m);
                    }
                }
            }
        }
        if (lane == 0) g_cnt[i] = cnt < NSAMPLE ? cnt : NSAMPLE;
    }

    // ---- last-block fused scan ----
    __threadfence();
    __syncthreads();
    __shared__ int s_last;
    if (tid == 0) s_last = (atomicAdd(&g_arrive, 1) == nblocks - 1) ? 1 : 0;
    __syncthreads();
    if (s_last) {
        __shared__ int wsum[8];
        const int PER = MAXN / 256;   // 16 (blockDim must be 256)
        int wid = tid >> 5;
        int base = tid * PER;
        int vals[PER];
        int tot = 0;
#pragma unroll
        for (int k = 0; k < PER; ++k) {
            int idx = base + k;
            int v = (idx < N) ? __ldcg(&g_cnt[idx]) : 0;
            vals[k] = v;
            tot += v;
        }
        int inc = tot;
#pragma unroll
        for (int d = 1; d < 32; d <<= 1) {
            int y = __shfl_up_sync(FULL, inc, d);
            if (lane >= d) inc += y;
        }
        if (lane == 31) wsum[wid] = inc;
        __syncthreads();
        int wpre = 0;
#pragma unroll
        for (int w = 0; w < 8; ++w)
            if (w < wid) wpre += wsum[w];
        int run = wpre + inc - tot;
#pragma unroll
        for (int k = 0; k < PER; ++k) {
            int idx = base + k;
            if (idx < N) g_off[idx] = run;
            run += vals[k];
        }
        if (tid == 255) g_total = wpre + inc;
        __syncthreads();
        if (tid == 0) g_arrive = 0;   // reset for next graph replay
    }
}

// ---------------------------------------------------------------------------
// Fallback generic query (R1 version) + separate scan, for unexpected shapes
// ---------------------------------------------------------------------------
__global__ void query_kernel_generic(const float* __restrict__ xyz,
                                     const float* __restrict__ new_xyz,
                                     const float* __restrict__ rois,
                                     int N, int Nb, int M, int K) {
    int warp = (blockIdx.x * blockDim.x + threadIdx.x) >> 5;
    int lane = threadIdx.x & 31;
    if (warp >= N) return;
    int i = warp;
    float px = xyz[3 * i + 0], py = xyz[3 * i + 1], pz = xyz[3 * i + 2];
    int b = i / Nb;
    int MK = M * K;
    const float* roib  = rois    + (size_t)b * M * 7;
    const float* gridb = new_xyz + (size_t)b * MK * 3;
    int cnt = 0;
    int ngroups = (M + 31) >> 5;
    for (int g = 0; g < ngroups && cnt < NSAMPLE; ++g) {
        int r = (g << 5) + lane;
        bool ib = false;
        if (r < M) {
            const float* ro = roib + (size_t)r * 7;
            float dx = px - ro[0], dy = py - ro[1], dz = pz - ro[2];
            float d2b = __fadd_rn(__fadd_rn(__fmul_rn(dx, dx), __fmul_rn(dy, dy)), __fmul_rn(dz, dz));
            float r2  = __fadd_rn(__fadd_rn(__fmul_rn(ro[3], ro[3]), __fmul_rn(ro[4], ro[4])), __fmul_rn(ro[5], ro[5]));
            ib = (d2b <= r2);
        }
        unsigned rm = __ballot_sync(FULL, ib);
        while (rm && cnt < NSAMPLE) {
            int rb = __ffs(rm) - 1;
            rm &= rm - 1;
            int basej = ((g << 5) + rb) * K;
            int nchunks = (K + 31) >> 5;
            for (int c = 0; c < nchunks && cnt < NSAMPLE; ++c) {
                int jl = (c << 5) + lane;
                bool ok = false;
                if (jl < K) {
                    const float* gp = gridb + (size_t)(basej + jl) * 3;
                    float dx = px - gp[0], dy = py - gp[1], dz = pz - gp[2];
                    float d2 = __fadd_rn(__fadd_rn(__fmul_rn(dx, dx), __fmul_rn(dy, dy)), __fmul_rn(dz, dz));
                    ok = (d2 <= 1.0f);
                }
                unsigned m = __ballot_sync(FULL, ok);
                int rank = cnt + __popc(m & ((1u << lane) - 1u));
                if (ok && rank < NSAMPLE)
                    g_ball[i * NSAMPLE + rank] = b * MK + basej + jl;
                cnt += __popc(m);
            }
        }
    }
    if (lane == 0) g_cnt[i] = cnt < NSAMPLE ? cnt : NSAMPLE;
}

__global__ void scan_kernel_generic(int N) {
    __shared__ int wsum[4];
    int t = threadIdx.x, lane = t & 31, wid = t >> 5;
    const int PER = MAXN / 128;
    int base = t * PER;
    int vals[PER]; int tot = 0;
#pragma unroll
    for (int k = 0; k < PER; ++k) {
        int idx = base + k;
        int v = (idx < N) ? g_cnt[idx] : 0;
        vals[k] = v; tot += v;
    }
    int inc = tot;
#pragma unroll
    for (int d = 1; d < 32; d <<= 1) {
        int y = __shfl_up_sync(FULL, inc, d);
        if (lane >= d) inc += y;
    }
    if (lane == 31) wsum[wid] = inc;
    __syncthreads();
    int wpre = 0;
#pragma unroll
    for (int w = 0; w < 4; ++w) if (w < wid) wpre += wsum[w];
    int run = wpre + inc - tot;
#pragma unroll
    for (int k = 0; k < PER; ++k) {
        int idx = base + k;
        if (idx < N) g_off[idx] = run;
        run += vals[k];
    }
    if (t == 127) g_total = wpre + inc;
}

// ---------------------------------------------------------------------------
// Scatter: block-per-point coalesced writes + tail-zero blocks
// ---------------------------------------------------------------------------
#define SCT_THREADS 128
#define ZBLK 1024

__global__ void scatter_kernel(const float* __restrict__ xyz,
                               const float* __restrict__ new_xyz_flat,
                               const float* __restrict__ feat,
                               float* __restrict__ out_gf,
                               float* __restrict__ out_idx,
                               int N, int C, int L) {
    int blk = blockIdx.x;
    int t = threadIdx.x;
    int D = 3 + C;

    if (blk < N) {
        __shared__ int   sball[NSAMPLE];
        __shared__ float sval[67];
        int i = blk;
        int cnt = g_cnt[i];
        if (cnt == 0) return;
        int off = g_off[i];

        if (t < cnt) sball[t] = g_ball[i * NSAMPLE + t];
        if (t < 3)   sval[t] = xyz[3 * i + t];
        if (t < C)   sval[3 + t] = feat[(size_t)i * C + t];
        __syncthreads();

        int total = cnt * D;
        float* dst = out_gf + (size_t)off * D;
        for (int e = t; e < total; e += SCT_THREADS) {
            int row = e / D;
            int col = e - row * D;
            float v = sval[col];
            if (col < 3)
                v -= new_xyz_flat[(size_t)sball[row] * 3 + col];
            dst[e] = v;
        }
        if (t < cnt) out_idx[off + t] = (float)sball[t];
    } else {
        int zb = blk - N;
        int nind = g_total;
        long S = (long)nind * D;
        long E = (long)L * D;
        long gt = (long)zb * SCT_THREADS + t;
        long TOT = (long)ZBLK * SCT_THREADS;
        long S4 = (S + 3) & ~3L;
        if (S4 > E) S4 = E;
        if (gt < (S4 - S)) out_gf[S + gt] = 0.f;
        float4 z4 = make_float4(0.f, 0.f, 0.f, 0.f);
        long n4 = (E - S4) >> 2;
        float4* p4 = (float4*)(out_gf + S4);
        for (long q = gt; q < n4; q += TOT) p4[q] = z4;
        long rem = (E - S4) & 3L;
        if (gt < rem) out_gf[S4 + (n4 << 2) + gt] = 0.f;
        for (long q = nind + gt; q < L; q += TOT) out_idx[q] = 0.f;
    }
}

// ---------------------------------------------------------------------------
extern "C" void kernel_launch(void* const* d_in, const int* in_sizes, int n_in,
                              void* d_out, int out_size) {
    const float* xyz     = (const float*)d_in[0];
    const float* new_xyz = (const float*)d_in[2];
    const float* rois    = (const float*)d_in[3];
    const float* feats   = (const float*)d_in[4];

    int N  = in_sizes[0] / 3;
    int B  = in_sizes[1];
    int Nb = N / B;
    int M  = in_sizes[3] / (B * 7);
    int K  = in_sizes[2] / (B * M * 3);
    int C  = in_sizes[4] / N;
    int L  = N * NSAMPLE;
    int D  = 3 + C;
    int BM = B * M;

    int nthreads = N * 32;
    int nblocks = (nthreads + 255) / 256;
    int nch = (K + 31) / 32;

    bool fused = (BM <= 1024) && (N <= MAXN) && (nch >= 1) && (nch <= 8);
    if (fused) {
        switch (nch) {
        case 1: query_scan_kernel<1><<<nblocks, 256>>>(xyz, new_xyz, rois, N, Nb, M, K, BM, nblocks); break;
        case 2: query_scan_kernel<2><<<nblocks, 256>>>(xyz, new_xyz, rois, N, Nb, M, K, BM, nblocks); break;
        case 3: query_scan_kernel<3><<<nblocks, 256>>>(xyz, new_xyz, rois, N, Nb, M, K, BM, nblocks); break;
        case 4: query_scan_kernel<4><<<nblocks, 256>>>(xyz, new_xyz, rois, N, Nb, M, K, BM, nblocks); break;
        case 5: query_scan_kernel<5><<<nblocks, 256>>>(xyz, new_xyz, rois, N, Nb, M, K, BM, nblocks); break;
        case 6: query_scan_kernel<6><<<nblocks, 256>>>(xyz, new_xyz, rois, N, Nb, M, K, BM, nblocks); break;
        case 7: query_scan_kernel<7><<<nblocks, 256>>>(xyz, new_xyz, rois, N, Nb, M, K, BM, nblocks); break;
        default: query_scan_kernel<8><<<nblocks, 256>>>(xyz, new_xyz, rois, N, Nb, M, K, BM, nblocks); break;
        }
    } else {
        query_kernel_generic<<<nblocks, 256>>>(xyz, new_xyz, rois, N, Nb, M, K);
        scan_kernel_generic<<<1, 128>>>(N);
    }

    scatter_kernel<<<N + ZBLK, SCT_THREADS>>>(
        xyz, new_xyz, feats,
        (float*)d_out, (float*)d_out + (size_t)L * D, N, C, L);
}